// round 11
// baseline (speedup 1.0000x reference)
#include <cuda_runtime.h>

// LIF neuron with cache term (final-form kernel, at the measured roofline):
//   mem   = mem/TAU + (1 + ALPHA*cache) * x_t
//   spike = (mem - V_TH > 0); mem = (1-spike)*mem; cache = BETA*cache + (1-spike)
//
// X: [B=32, T=64, N=32768] f32 -> spikes, same shape. Pure streaming,
// 512 MiB compulsory traffic, 1:1 read:write.
//
// Session findings (R4-R10): six mechanistically distinct variants
// (register-pipeline depth, L2 prefetch, cp.async SMEM ring, exact CTA
// balance, 256-bit v8 ops, dual distant streams) all pin DRAM at
// 73-76% active / ~6.0 TB/s, kernel 80-81 us = 512MiB / achieved BW.
// That is the B300 effective ceiling for a fine-grained 1:1 R/W mix
// (8 TB/s spec is unidirectional). R11 change: peel the final loop
// iteration so the prefetch clamp no longer re-reads row T-1 (removes
// 4 MiB of redundant DRAM reads and the per-iteration min).
//
// Division by TAU=5 via residual-corrected FMA triple — provably
// bit-identical to __fdiv_rn(x,5) for all floats (true quotient is
// >= 1/10 ulp from any rounding midpoint; sequence error ~2^-25 ulp).
// All other ops use explicit __f*_rn (no FMA contraction) to bit-match
// the XLA reference — a single threshold flip would cascade down the
// whole T recurrence. rel_err has been exactly 0.0 on every run.

constexpr int B = 32;
constexpr int T = 64;
constexpr int N = 32768;
constexpr int N4 = N / 4;           // 8192 float4 per (b, t) row

__device__ __forceinline__ float div5_exact(float x) {
    const float y = 0.2f;                       // RN(1/5)
    float q = __fmul_rn(x, y);
    float r = __fmaf_rn(q, -5.0f, x);           // exact residual
    return __fmaf_rn(r, y, q);                  // == __fdiv_rn(x, 5.0f)
}

__device__ __forceinline__ float lif_step(float x, float& mem, float& cache) {
    float d = div5_exact(mem);                              // mem / TAU
    float g = __fadd_rn(1.0f, __fmul_rn(0.1f, cache));      // 1 + ALPHA*cache
    mem = __fadd_rn(d, __fmul_rn(g, x));
    bool fired = (mem > 0.5f);                              // mem - V_TH > 0
    float spike = fired ? 1.0f : 0.0f;
    mem = fired ? 0.0f : mem;                               // hard reset to 0
    cache = __fadd_rn(__fmul_rn(0.5f, cache), fired ? 0.0f : 1.0f);
    return spike;
}

__device__ __forceinline__ float4 step4(float4 x, float4& mem, float4& cache) {
    float4 s;
    s.x = lif_step(x.x, mem.x, cache.x);
    s.y = lif_step(x.y, mem.y, cache.y);
    s.z = lif_step(x.z, mem.z, cache.z);
    s.w = lif_step(x.w, mem.w, cache.w);
    return s;
}

__global__ __launch_bounds__(256) void lif_kernel(
    const float4* __restrict__ X, float4* __restrict__ out)
{
    int lane = blockIdx.x * blockDim.x + threadIdx.x;   // [0, B*N4)
    int b = lane >> 13;                                  // lane / N4
    int c = lane & (N4 - 1);                             // lane % N4
    int base = b * (T * N4) + c;

    float4 mem   = make_float4(0.f, 0.f, 0.f, 0.f);
    float4 cache = make_float4(0.f, 0.f, 0.f, 0.f);

    // Prefetch pipeline: x holds step-t data; step-(t+1) load is in
    // flight during the step-t compute body. Last iteration peeled so
    // no clamped/redundant prefetch is ever issued.
    float4 x = __ldcs(&X[base]);

#pragma unroll 7
    for (int t = 0; t < T - 1; ++t) {
        float4 xn = __ldcs(&X[base + (t + 1) * N4]);
        float4 s = step4(x, mem, cache);
        __stcs(&out[base + t * N4], s);
        x = xn;
    }
    // Peeled final step: no prefetch.
    float4 s = step4(x, mem, cache);
    __stcs(&out[base + (T - 1) * N4], s);
}

extern "C" void kernel_launch(void* const* d_in, const int* in_sizes, int n_in,
                              void* d_out, int out_size) {
    const float4* X = (const float4*)d_in[0];
    float4* out = (float4*)d_out;
    int lanes = B * N4;                 // 262,144
    lif_kernel<<<lanes / 256, 256>>>(X, out);
}